// round 4
// baseline (speedup 1.0000x reference)
#include <cuda_runtime.h>

// Problem constants (fixed shapes from setup_inputs)
#define BB 2
#define CC 3
#define HH 512
#define WW 512
#define FF 5
#define TT 25
#define HWSZ (HH * WW)

__global__ __launch_bounds__(256) void dsepconv_kernel(
    const float* __restrict__ inp,     // [B,C,H,W]
    const float* __restrict__ vert,    // [B,F,H,W]
    const float* __restrict__ horiz,   // [B,F,H,W]
    const float* __restrict__ offx,    // [B,T,H,W]  (used for y coordinate)
    const float* __restrict__ offy,    // [B,T,H,W]  (used for x coordinate)
    const float* __restrict__ mask,    // [B,T,H,W]
    float* __restrict__ out)           // [B,C,H,W]
{
    int tid = blockIdx.x * blockDim.x + threadIdx.x;
    // tid covers B*H*W = 524288
    int b = tid >> 18;            // H*W = 2^18
    int p = tid & (HWSZ - 1);
    int h = p >> 9;               // W = 2^9
    int w = p & (WW - 1);

    const float* __restrict__ inb = inp + b * (CC * HWSZ);

    // Preload separable filter values for this pixel
    float vv[FF], hh[FF];
#pragma unroll
    for (int f = 0; f < FF; f++) {
        vv[f] = __ldg(vert  + (b * FF + f) * HWSZ + p);
        hh[f] = __ldg(horiz + (b * FF + f) * HWSZ + p);
    }

    const float* __restrict__ oxp = offx + b * (TT * HWSZ) + p;
    const float* __restrict__ oyp = offy + b * (TT * HWSZ) + p;
    const float* __restrict__ mkp = mask + b * (TT * HWSZ) + p;

    float acc0 = 0.f, acc1 = 0.f, acc2 = 0.f;

#pragma unroll
    for (int t = 0; t < TT; t++) {
        const int fy = t / FF;
        const int fx = t % FF;

        float o_x = __ldg(oxp + t * HWSZ);   // goes to y coordinate (faithful swap)
        float o_y = __ldg(oyp + t * HWSZ);   // goes to x coordinate
        float m   = __ldg(mkp + t * HWSZ);

        // Reference: x_norm = clip(2*(offy + w + fx - (F-1)/2 + 1)/W - 1, -1, 1)
        //            ix = ((x_norm+1)*W - 1)/2
        // Algebraically: ix = clamp(u - 0.5, -0.5, W - 0.5) with u = offy + w + fx - 1
        float u = o_y + (float)(w + fx) - 1.0f;
        float v = o_x + (float)(h + fy) - 1.0f;
        float ix = fminf(fmaxf(u - 0.5f, -0.5f), (float)WW - 0.5f);
        float iy = fminf(fmaxf(v - 0.5f, -0.5f), (float)HH - 0.5f);

        float fx0 = floorf(ix);
        float fy0 = floorf(iy);
        float wx1 = ix - fx0;
        float wy1 = iy - fy0;
        float wx0 = 1.0f - wx1;
        float wy0 = 1.0f - wy1;

        int x0 = (int)fx0;
        int y0 = (int)fy0;
        int x0i = min(max(x0,     0), WW - 1);
        int x1i = min(max(x0 + 1, 0), WW - 1);
        int y0i = min(max(y0,     0), HH - 1);
        int y1i = min(max(y0 + 1, 0), HH - 1);

        float coef = vv[fy] * hh[fx] * m;
        float w00 = coef * wy0 * wx0;
        float w01 = coef * wy0 * wx1;
        float w10 = coef * wy1 * wx0;
        float w11 = coef * wy1 * wx1;

        int r0 = y0i * WW;
        int r1 = y1i * WW;
        int i00 = r0 + x0i;
        int i01 = r0 + x1i;
        int i10 = r1 + x0i;
        int i11 = r1 + x1i;

        // channel 0
        {
            const float* c = inb;
            acc0 = fmaf(w00, __ldg(c + i00), acc0);
            acc0 = fmaf(w01, __ldg(c + i01), acc0);
            acc0 = fmaf(w10, __ldg(c + i10), acc0);
            acc0 = fmaf(w11, __ldg(c + i11), acc0);
        }
        // channel 1
        {
            const float* c = inb + HWSZ;
            acc1 = fmaf(w00, __ldg(c + i00), acc1);
            acc1 = fmaf(w01, __ldg(c + i01), acc1);
            acc1 = fmaf(w10, __ldg(c + i10), acc1);
            acc1 = fmaf(w11, __ldg(c + i11), acc1);
        }
        // channel 2
        {
            const float* c = inb + 2 * HWSZ;
            acc2 = fmaf(w00, __ldg(c + i00), acc2);
            acc2 = fmaf(w01, __ldg(c + i01), acc2);
            acc2 = fmaf(w10, __ldg(c + i10), acc2);
            acc2 = fmaf(w11, __ldg(c + i11), acc2);
        }
    }

    float* ob = out + b * (CC * HWSZ) + p;
    ob[0]         = acc0;
    ob[HWSZ]      = acc1;
    ob[2 * HWSZ]  = acc2;
}

extern "C" void kernel_launch(void* const* d_in, const int* in_sizes, int n_in,
                              void* d_out, int out_size) {
    const float* inp   = (const float*)d_in[0];
    const float* vert  = (const float*)d_in[1];
    const float* horiz = (const float*)d_in[2];
    const float* offx  = (const float*)d_in[3];
    const float* offy  = (const float*)d_in[4];
    const float* mask  = (const float*)d_in[5];
    float* out = (float*)d_out;

    const int total = BB * HWSZ;            // 524288 threads
    const int block = 256;
    const int grid = total / block;         // 2048
    dsepconv_kernel<<<grid, block>>>(inp, vert, horiz, offx, offy, mask, out);
}